// round 5
// baseline (speedup 1.0000x reference)
#include <cuda_runtime.h>
#include <cstdint>

// Per-voxel 4th-order tensor transform:
//   C[b,i,j,k,l,v] = sum_{m,n,o,p} a[b,m,i,v] a[b,n,j,v] a[b,o,k,v] a[b,p,l,v] C0[m,n,o,p]
// Staged as two fused double-contractions to keep only one 81-float intermediate live.

static constexpr int G3 = 64 * 64 * 64;  // 262144 voxels per batch

__global__ void alphaC0_kernel(const float* __restrict__ alpha,
                               const float* __restrict__ C0,
                               float* __restrict__ out,
                               int n_vox) {
    __shared__ float sC0[81];
    int tid = threadIdx.x;
    if (tid < 81) sC0[tid] = C0[tid];
    __syncthreads();

    int v = blockIdx.x * blockDim.x + tid;
    if (v >= n_vox) return;

    int b = v >> 18;            // v / G3
    int s = v & (G3 - 1);       // v % G3

    const float* ap = alpha + (size_t)b * 9 * G3 + s;
    float a[9];                 // a[m*3+i] = a_{m,i}
#pragma unroll
    for (int q = 0; q < 9; q++) a[q] = ap[(size_t)q * G3];

    // Fused stages 1+2: t2[o,p,i,j] = sum_n a[n,j] * (sum_m a[m,i] * C0[m,n,o,p])
    float t2[81];               // t2[((o*3+p)*3+i)*3+j]
#pragma unroll
    for (int o = 0; o < 3; o++) {
#pragma unroll
        for (int p = 0; p < 3; p++) {
#pragma unroll
            for (int i = 0; i < 3; i++) {
                float t0 = 0.f, t1 = 0.f, t2n = 0.f;   // t[n] = sum_m a[m,i]*C0[m,n,o,p]
#pragma unroll
                for (int m = 0; m < 3; m++) {
                    float am = a[m * 3 + i];
                    t0 = fmaf(am, sC0[((m * 3 + 0) * 3 + o) * 3 + p], t0);
                    t1 = fmaf(am, sC0[((m * 3 + 1) * 3 + o) * 3 + p], t1);
                    t2n = fmaf(am, sC0[((m * 3 + 2) * 3 + o) * 3 + p], t2n);
                }
#pragma unroll
                for (int j = 0; j < 3; j++) {
                    t2[((o * 3 + p) * 3 + i) * 3 + j] =
                        fmaf(a[0 * 3 + j], t0, fmaf(a[1 * 3 + j], t1, a[2 * 3 + j] * t2n));
                }
            }
        }
    }

    // Fused stages 3+4: C[i,j,k,l] = sum_p a[p,l] * (sum_o a[o,k] * t2[o,p,i,j])
    float* op = out + (size_t)b * 81 * G3 + s;
#pragma unroll
    for (int i = 0; i < 3; i++) {
#pragma unroll
        for (int j = 0; j < 3; j++) {
#pragma unroll
            for (int k = 0; k < 3; k++) {
                float u0 = 0.f, u1 = 0.f, u2 = 0.f;    // u[p] = sum_o a[o,k]*t2[o,p,i,j]
#pragma unroll
                for (int o = 0; o < 3; o++) {
                    float ao = a[o * 3 + k];
                    u0 = fmaf(ao, t2[((o * 3 + 0) * 3 + i) * 3 + j], u0);
                    u1 = fmaf(ao, t2[((o * 3 + 1) * 3 + i) * 3 + j], u1);
                    u2 = fmaf(ao, t2[((o * 3 + 2) * 3 + i) * 3 + j], u2);
                }
#pragma unroll
                for (int l = 0; l < 3; l++) {
                    float c = fmaf(a[0 * 3 + l], u0, fmaf(a[1 * 3 + l], u1, a[2 * 3 + l] * u2));
                    op[(size_t)(((i * 3 + j) * 3 + k) * 3 + l) * G3] = c;
                }
            }
        }
    }
}

extern "C" void kernel_launch(void* const* d_in, const int* in_sizes, int n_in,
                              void* d_out, int out_size) {
    const float* alpha = (const float*)d_in[0];
    const float* C0    = (const float*)d_in[1];
    float* out = (float*)d_out;

    int n_vox = in_sizes[0] / 9;   // B * G^3
    int threads = 256;
    int blocks = (n_vox + threads - 1) / threads;
    alphaC0_kernel<<<blocks, threads>>>(alpha, C0, out, n_vox);
}